// round 8
// baseline (speedup 1.0000x reference)
#include <cuda_runtime.h>
#include <cstdint>

// S_GCN: out[b,c,m] = relu( para[c,m] * sum_j x[b,c,j] * adj[j,m] * g(cadj[b,m]-cadj[b,j]) )
// with cadj = mean over channels, g(d) = 1 - |tanh(d/2)| = 2e/(1+e), e = exp(-|d|).
// (The reference's symmetrization is a no-op since g is even.)

#define BB 8
#define CC 32
#define NN 4096
#define MTILE 128
#define JC 32
#define NTHREADS 128

typedef unsigned long long ull;

__device__ float g_cadj[BB * NN];   // scratch: channel means, [b][n]

__device__ __forceinline__ ull pack2(float v) {
    ull r;
    asm("mov.b64 %0, {%1, %1};" : "=l"(r) : "f"(v));
    return r;
}
__device__ __forceinline__ void fma2(ull& d, ull a, ull b) {
    asm("fma.rn.f32x2 %0, %1, %2, %0;" : "+l"(d) : "l"(a), "l"(b));
}
__device__ __forceinline__ float2 unpack2(ull v) {
    float2 r;
    asm("mov.b64 {%0, %1}, %2;" : "=f"(r.x), "=f"(r.y) : "l"(v));
    return r;
}

// g(d) = 2e/(1+e), e = exp(-|d|). ~2 ulp via MUFU ex2 + rcp.
__device__ __forceinline__ float gfun(float d) {
    float e = __expf(-fabsf(d));
    return __fdividef(2.0f * e, 1.0f + e);
}

__global__ void cadj_kernel(const float* __restrict__ x) {
    int idx = blockIdx.x * blockDim.x + threadIdx.x;   // 0 .. B*N-1
    int b = idx >> 12;
    int n = idx & (NN - 1);
    const float* p = x + (size_t)b * CC * NN + n;
    float s = 0.0f;
#pragma unroll
    for (int c = 0; c < CC; ++c) s += p[(size_t)c * NN];
    g_cadj[idx] = s * (1.0f / CC);
}

__global__ void __launch_bounds__(NTHREADS) gcn_kernel(
    const float* __restrict__ x, const float* __restrict__ para,
    const float* __restrict__ adj, float* __restrict__ out)
{
    __shared__ __align__(16) float w_s[JC][MTILE];   // 16 KB: A-tile [jc][m]
    __shared__ __align__(16) float fea_s[JC][36];    // fea transposed [jc][c], padded stride
    __shared__ float cm_s[MTILE];                    // cadj for this m-tile

    const int b = blockIdx.y;
    const int m_base = blockIdx.x * MTILE;
    const int tid = threadIdx.x;
    const int cg = tid >> 5;          // warp -> c-group (8 channels)
    const int lane = tid & 31;        // lane -> m-group (4 consecutive m)
    const int c0 = cg << 3;
    const int m0 = lane << 2;

    cm_s[tid] = g_cadj[b * NN + m_base + tid];   // NTHREADS == MTILE

    const float* feaB = x + (size_t)b * CC * NN;
    const float* cadjB = g_cadj + b * NN;

    ull acc[4][4];
#pragma unroll
    for (int i = 0; i < 4; ++i)
#pragma unroll
        for (int j = 0; j < 4; ++j) acc[i][j] = 0ULL;

    for (int j0 = 0; j0 < NN; j0 += JC) {
        __syncthreads();   // previous FMA phase done (and cm_s visible on iter 0)

        // ---- stage fea: transpose 32c x 32j into fea_s[jc][c] ----
#pragma unroll
        for (int it = 0; it < 2; ++it) {
            int i = tid + it * NTHREADS;          // 0..255
            int ccc = i >> 3;
            int jj = (i & 7) << 2;
            float4 f = *reinterpret_cast<const float4*>(&feaB[(size_t)ccc * NN + j0 + jj]);
            fea_s[jj + 0][ccc] = f.x;
            fea_s[jj + 1][ccc] = f.y;
            fea_s[jj + 2][ccc] = f.z;
            fea_s[jj + 3][ccc] = f.w;
        }

        // ---- stage w: w_s[jc][m] = adj[j,m] * g(cm - cj) ----
#pragma unroll
        for (int it = 0; it < 8; ++it) {
            int i = tid + it * NTHREADS;          // 0..1023
            int jc = i >> 5;
            int m4 = (i & 31) << 2;
            int jg = j0 + jc;
            float cj = __ldg(&cadjB[jg]);         // warp-broadcast
            float4 a4 = *reinterpret_cast<const float4*>(&adj[(size_t)jg * NN + m_base + m4]);
            float4 w4;
            w4.x = a4.x * gfun(cm_s[m4 + 0] - cj);
            w4.y = a4.y * gfun(cm_s[m4 + 1] - cj);
            w4.z = a4.z * gfun(cm_s[m4 + 2] - cj);
            w4.w = a4.w * gfun(cm_s[m4 + 3] - cj);
            *reinterpret_cast<float4*>(&w_s[jc][m4]) = w4;
        }
        __syncthreads();

        // ---- FMA phase: 8c x 4m register tile, packed f32x2 FMAs ----
#pragma unroll 4
        for (int jc = 0; jc < JC; ++jc) {
            ulonglong2 f1 = *reinterpret_cast<const ulonglong2*>(&fea_s[jc][c0]);      // broadcast
            ulonglong2 f2 = *reinterpret_cast<const ulonglong2*>(&fea_s[jc][c0 + 4]);  // broadcast
            float4 wv = *reinterpret_cast<const float4*>(&w_s[jc][m0]);                // conflict-free
            ull wp[4];
            wp[0] = pack2(wv.x); wp[1] = pack2(wv.y);
            wp[2] = pack2(wv.z); wp[3] = pack2(wv.w);
            ull fp[4];
            fp[0] = f1.x; fp[1] = f1.y; fp[2] = f2.x; fp[3] = f2.y;
#pragma unroll
            for (int cp = 0; cp < 4; ++cp)
#pragma unroll
                for (int mi = 0; mi < 4; ++mi)
                    fma2(acc[cp][mi], fp[cp], wp[mi]);
        }
    }

    // ---- epilogue: * para, relu, store ----
    float* outB = out + (size_t)b * CC * NN;
#pragma unroll
    for (int cp = 0; cp < 4; ++cp) {
        int ce = c0 + 2 * cp;
#pragma unroll
        for (int mi = 0; mi < 4; ++mi) {
            int m = m_base + m0 + mi;
            float2 v = unpack2(acc[cp][mi]);
            float pe = para[ce * NN + m];
            float po = para[(ce + 1) * NN + m];
            outB[(size_t)ce * NN + m]       = fmaxf(v.x * pe, 0.0f);
            outB[(size_t)(ce + 1) * NN + m] = fmaxf(v.y * po, 0.0f);
        }
    }
}

extern "C" void kernel_launch(void* const* d_in, const int* in_sizes, int n_in,
                              void* d_out, int out_size)
{
    const float* x    = (const float*)d_in[0];   // [8,32,64,64]
    const float* para = (const float*)d_in[1];   // [1,32,64,64]
    const float* adj  = (const float*)d_in[2];   // [4096,4096]
    float* out = (float*)d_out;                  // [8,32,64,64]

    cadj_kernel<<<(BB * NN) / 256, 256>>>(x);

    dim3 grid(NN / MTILE, BB);   // 32 x 8 = 256 CTAs
    gcn_kernel<<<grid, NTHREADS>>>(x, para, adj, out);
}

// round 9
// speedup vs baseline: 1.0084x; 1.0084x over previous
#include <cuda_runtime.h>
#include <cstdint>

// S_GCN: out[b,c,m] = relu( para[c,m] * sum_j x[b,c,j] * adj[j,m] * g(cadj[b,m]-cadj[b,j]) )
// with cadj = mean over channels, g(d) = 1 - |tanh(d/2)| = 2e/(1+e), e = exp(-|d|).
// (The reference's symmetrization is a no-op since g is even.)

#define BB 8
#define CC 32
#define NN 4096
#define MTILE 128
#define JC 32
#define NTHREADS 128

typedef unsigned long long ull;

__device__ float g_cadj[BB * NN];   // scratch: channel means, [b][n]

__device__ __forceinline__ ull pack2(float v) {
    ull r;
    asm("mov.b64 %0, {%1, %1};" : "=l"(r) : "f"(v));
    return r;
}
__device__ __forceinline__ void fma2(ull& d, ull a, ull b) {
    asm("fma.rn.f32x2 %0, %1, %2, %0;" : "+l"(d) : "l"(a), "l"(b));
}
__device__ __forceinline__ float2 unpack2(ull v) {
    float2 r;
    asm("mov.b64 {%0, %1}, %2;" : "=f"(r.x), "=f"(r.y) : "l"(v));
    return r;
}

// g(d) = 2e/(1+e), e = exp(-|d|). ~2 ulp via MUFU ex2 + rcp.
__device__ __forceinline__ float gfun(float d) {
    float e = __expf(-fabsf(d));
    return __fdividef(2.0f * e, 1.0f + e);
}

__global__ void cadj_kernel(const float* __restrict__ x) {
    int idx = blockIdx.x * blockDim.x + threadIdx.x;   // 0 .. B*N-1
    int b = idx >> 12;
    int n = idx & (NN - 1);
    const float* p = x + (size_t)b * CC * NN + n;
    float s = 0.0f;
#pragma unroll
    for (int c = 0; c < CC; ++c) s += p[(size_t)c * NN];
    g_cadj[idx] = s * (1.0f / CC);
}

__global__ void __launch_bounds__(NTHREADS) gcn_kernel(
    const float* __restrict__ x, const float* __restrict__ para,
    const float* __restrict__ adj, float* __restrict__ out)
{
    __shared__ __align__(16) float w_s[JC][MTILE];   // 16 KB: A-tile [jc][m]
    __shared__ __align__(16) float fea_s[JC][36];    // fea transposed [jc][c], padded stride
    __shared__ float cm_s[MTILE];                    // cadj for this m-tile

    const int b = blockIdx.y;
    const int m_base = blockIdx.x * MTILE;
    const int tid = threadIdx.x;
    const int cg = tid >> 5;          // warp -> c-group (8 channels)
    const int lane = tid & 31;        // lane -> m-group (4 consecutive m)
    const int c0 = cg << 3;
    const int m0 = lane << 2;

    cm_s[tid] = g_cadj[b * NN + m_base + tid];   // NTHREADS == MTILE

    const float* feaB = x + (size_t)b * CC * NN;
    const float* cadjB = g_cadj + b * NN;

    ull acc[4][4];
#pragma unroll
    for (int i = 0; i < 4; ++i)
#pragma unroll
        for (int j = 0; j < 4; ++j) acc[i][j] = 0ULL;

    for (int j0 = 0; j0 < NN; j0 += JC) {
        __syncthreads();   // previous FMA phase done (and cm_s visible on iter 0)

        // ---- stage fea: transpose 32c x 32j into fea_s[jc][c] ----
#pragma unroll
        for (int it = 0; it < 2; ++it) {
            int i = tid + it * NTHREADS;          // 0..255
            int ccc = i >> 3;
            int jj = (i & 7) << 2;
            float4 f = *reinterpret_cast<const float4*>(&feaB[(size_t)ccc * NN + j0 + jj]);
            fea_s[jj + 0][ccc] = f.x;
            fea_s[jj + 1][ccc] = f.y;
            fea_s[jj + 2][ccc] = f.z;
            fea_s[jj + 3][ccc] = f.w;
        }

        // ---- stage w: w_s[jc][m] = adj[j,m] * g(cm - cj) ----
#pragma unroll
        for (int it = 0; it < 8; ++it) {
            int i = tid + it * NTHREADS;          // 0..1023
            int jc = i >> 5;
            int m4 = (i & 31) << 2;
            int jg = j0 + jc;
            float cj = __ldg(&cadjB[jg]);         // warp-broadcast
            float4 a4 = *reinterpret_cast<const float4*>(&adj[(size_t)jg * NN + m_base + m4]);
            float4 w4;
            w4.x = a4.x * gfun(cm_s[m4 + 0] - cj);
            w4.y = a4.y * gfun(cm_s[m4 + 1] - cj);
            w4.z = a4.z * gfun(cm_s[m4 + 2] - cj);
            w4.w = a4.w * gfun(cm_s[m4 + 3] - cj);
            *reinterpret_cast<float4*>(&w_s[jc][m4]) = w4;
        }
        __syncthreads();

        // ---- FMA phase: 8c x 4m register tile, packed f32x2 FMAs ----
#pragma unroll 4
        for (int jc = 0; jc < JC; ++jc) {
            ulonglong2 f1 = *reinterpret_cast<const ulonglong2*>(&fea_s[jc][c0]);      // broadcast
            ulonglong2 f2 = *reinterpret_cast<const ulonglong2*>(&fea_s[jc][c0 + 4]);  // broadcast
            float4 wv = *reinterpret_cast<const float4*>(&w_s[jc][m0]);                // conflict-free
            ull wp[4];
            wp[0] = pack2(wv.x); wp[1] = pack2(wv.y);
            wp[2] = pack2(wv.z); wp[3] = pack2(wv.w);
            ull fp[4];
            fp[0] = f1.x; fp[1] = f1.y; fp[2] = f2.x; fp[3] = f2.y;
#pragma unroll
            for (int cp = 0; cp < 4; ++cp)
#pragma unroll
                for (int mi = 0; mi < 4; ++mi)
                    fma2(acc[cp][mi], fp[cp], wp[mi]);
        }
    }

    // ---- epilogue: * para, relu, store ----
    float* outB = out + (size_t)b * CC * NN;
#pragma unroll
    for (int cp = 0; cp < 4; ++cp) {
        int ce = c0 + 2 * cp;
#pragma unroll
        for (int mi = 0; mi < 4; ++mi) {
            int m = m_base + m0 + mi;
            float2 v = unpack2(acc[cp][mi]);
            float pe = para[ce * NN + m];
            float po = para[(ce + 1) * NN + m];
            outB[(size_t)ce * NN + m]       = fmaxf(v.x * pe, 0.0f);
            outB[(size_t)(ce + 1) * NN + m] = fmaxf(v.y * po, 0.0f);
        }
    }
}

extern "C" void kernel_launch(void* const* d_in, const int* in_sizes, int n_in,
                              void* d_out, int out_size)
{
    const float* x    = (const float*)d_in[0];   // [8,32,64,64]
    const float* para = (const float*)d_in[1];   // [1,32,64,64]
    const float* adj  = (const float*)d_in[2];   // [4096,4096]
    float* out = (float*)d_out;                  // [8,32,64,64]

    cadj_kernel<<<(BB * NN) / 256, 256>>>(x);

    dim3 grid(NN / MTILE, BB);   // 32 x 8 = 256 CTAs
    gcn_kernel<<<grid, NTHREADS>>>(x, para, adj, out);
}

// round 10
// speedup vs baseline: 1.0180x; 1.0095x over previous
#include <cuda_runtime.h>
#include <cstdint>

// S_GCN: out[b,c,m] = relu( para[c,m] * sum_j x[b,c,j] * adj[j,m] * g(cadj[b,m]-cadj[b,j]) )
// with cadj = mean over channels, g(d) = 1 - |tanh(d/2)| = 2e/(1+e), e = exp(-|d|).
// (The reference's symmetrization is a no-op since g is even.)

#define BB 8
#define CC 32
#define NN 4096
#define MTILE 128
#define JC 32
#define NTHREADS 128

typedef unsigned long long ull;

__device__ float g_cadj[BB * NN];   // scratch: channel means, [b][n]

__device__ __forceinline__ ull pack2(float v) {
    ull r;
    asm("mov.b64 %0, {%1, %1};" : "=l"(r) : "f"(v));
    return r;
}
__device__ __forceinline__ void fma2(ull& d, ull a, ull b) {
    asm("fma.rn.f32x2 %0, %1, %2, %0;" : "+l"(d) : "l"(a), "l"(b));
}
__device__ __forceinline__ float2 unpack2(ull v) {
    float2 r;
    asm("mov.b64 {%0, %1}, %2;" : "=f"(r.x), "=f"(r.y) : "l"(v));
    return r;
}

// g(d) = 2e/(1+e), e = exp(-|d|). ~2 ulp via MUFU ex2 + rcp.
__device__ __forceinline__ float gfun(float d) {
    float e = __expf(-fabsf(d));
    return __fdividef(2.0f * e, 1.0f + e);
}

__global__ void cadj_kernel(const float* __restrict__ x) {
    int idx = blockIdx.x * blockDim.x + threadIdx.x;   // 0 .. B*N-1
    int b = idx >> 12;
    int n = idx & (NN - 1);
    const float* p = x + (size_t)b * CC * NN + n;
    float s = 0.0f;
#pragma unroll
    for (int c = 0; c < CC; ++c) s += p[(size_t)c * NN];
    g_cadj[idx] = s * (1.0f / CC);
}

__global__ void __launch_bounds__(NTHREADS) gcn_kernel(
    const float* __restrict__ x, const float* __restrict__ para,
    const float* __restrict__ adj, float* __restrict__ out)
{
    __shared__ __align__(16) float w_s[JC][MTILE];   // 16 KB: A-tile [jc][m]
    __shared__ __align__(16) float fea_s[JC][36];    // fea transposed [jc][c], padded stride
    __shared__ float cm_s[MTILE];                    // cadj for this m-tile

    const int b = blockIdx.y;
    const int m_base = blockIdx.x * MTILE;
    const int tid = threadIdx.x;
    const int cg = tid >> 5;          // warp -> c-group (8 channels)
    const int lane = tid & 31;        // lane -> m-group (4 consecutive m)
    const int c0 = cg << 3;
    const int m0 = lane << 2;

    cm_s[tid] = g_cadj[b * NN + m_base + tid];   // NTHREADS == MTILE

    const float* feaB = x + (size_t)b * CC * NN;
    const float* cadjB = g_cadj + b * NN;

    ull acc[4][4];
#pragma unroll
    for (int i = 0; i < 4; ++i)
#pragma unroll
        for (int j = 0; j < 4; ++j) acc[i][j] = 0ULL;

    for (int j0 = 0; j0 < NN; j0 += JC) {
        __syncthreads();   // previous FMA phase done (and cm_s visible on iter 0)

        // ---- stage fea: transpose 32c x 32j into fea_s[jc][c] ----
#pragma unroll
        for (int it = 0; it < 2; ++it) {
            int i = tid + it * NTHREADS;          // 0..255
            int ccc = i >> 3;
            int jj = (i & 7) << 2;
            float4 f = *reinterpret_cast<const float4*>(&feaB[(size_t)ccc * NN + j0 + jj]);
            fea_s[jj + 0][ccc] = f.x;
            fea_s[jj + 1][ccc] = f.y;
            fea_s[jj + 2][ccc] = f.z;
            fea_s[jj + 3][ccc] = f.w;
        }

        // ---- stage w: w_s[jc][m] = adj[j,m] * g(cm - cj) ----
#pragma unroll
        for (int it = 0; it < 8; ++it) {
            int i = tid + it * NTHREADS;          // 0..1023
            int jc = i >> 5;
            int m4 = (i & 31) << 2;
            int jg = j0 + jc;
            float cj = __ldg(&cadjB[jg]);         // warp-broadcast
            float4 a4 = *reinterpret_cast<const float4*>(&adj[(size_t)jg * NN + m_base + m4]);
            float4 w4;
            w4.x = a4.x * gfun(cm_s[m4 + 0] - cj);
            w4.y = a4.y * gfun(cm_s[m4 + 1] - cj);
            w4.z = a4.z * gfun(cm_s[m4 + 2] - cj);
            w4.w = a4.w * gfun(cm_s[m4 + 3] - cj);
            *reinterpret_cast<float4*>(&w_s[jc][m4]) = w4;
        }
        __syncthreads();

        // ---- FMA phase: 8c x 4m register tile, packed f32x2 FMAs ----
#pragma unroll 4
        for (int jc = 0; jc < JC; ++jc) {
            ulonglong2 f1 = *reinterpret_cast<const ulonglong2*>(&fea_s[jc][c0]);      // broadcast
            ulonglong2 f2 = *reinterpret_cast<const ulonglong2*>(&fea_s[jc][c0 + 4]);  // broadcast
            float4 wv = *reinterpret_cast<const float4*>(&w_s[jc][m0]);                // conflict-free
            ull wp[4];
            wp[0] = pack2(wv.x); wp[1] = pack2(wv.y);
            wp[2] = pack2(wv.z); wp[3] = pack2(wv.w);
            ull fp[4];
            fp[0] = f1.x; fp[1] = f1.y; fp[2] = f2.x; fp[3] = f2.y;
#pragma unroll
            for (int cp = 0; cp < 4; ++cp)
#pragma unroll
                for (int mi = 0; mi < 4; ++mi)
                    fma2(acc[cp][mi], fp[cp], wp[mi]);
        }
    }

    // ---- epilogue: * para, relu, store ----
    float* outB = out + (size_t)b * CC * NN;
#pragma unroll
    for (int cp = 0; cp < 4; ++cp) {
        int ce = c0 + 2 * cp;
#pragma unroll
        for (int mi = 0; mi < 4; ++mi) {
            int m = m_base + m0 + mi;
            float2 v = unpack2(acc[cp][mi]);
            float pe = para[ce * NN + m];
            float po = para[(ce + 1) * NN + m];
            outB[(size_t)ce * NN + m]       = fmaxf(v.x * pe, 0.0f);
            outB[(size_t)(ce + 1) * NN + m] = fmaxf(v.y * po, 0.0f);
        }
    }
}

extern "C" void kernel_launch(void* const* d_in, const int* in_sizes, int n_in,
                              void* d_out, int out_size)
{
    const float* x    = (const float*)d_in[0];   // [8,32,64,64]
    const float* para = (const float*)d_in[1];   // [1,32,64,64]
    const float* adj  = (const float*)d_in[2];   // [4096,4096]
    float* out = (float*)d_out;                  // [8,32,64,64]

    cadj_kernel<<<(BB * NN) / 256, 256>>>(x);

    dim3 grid(NN / MTILE, BB);   // 32 x 8 = 256 CTAs
    gcn_kernel<<<grid, NTHREADS>>>(x, para, adj, out);
}

// round 11
// speedup vs baseline: 1.0213x; 1.0033x over previous
#include <cuda_runtime.h>
#include <cstdint>

// S_GCN: out[b,c,m] = relu( para[c,m] * sum_j x[b,c,j] * adj[j,m] * g(cadj[b,m]-cadj[b,j]) )
// with cadj = mean over channels, g(d) = 1 - |tanh(d/2)| = 2e/(1+e), e = exp(-|d|).
// (The reference's symmetrization is a no-op since g is even.)

#define BB 8
#define CC 32
#define NN 4096
#define MTILE 128
#define JC 32
#define NTHREADS 128

typedef unsigned long long ull;

__device__ float g_cadj[BB * NN];   // scratch: channel means, [b][n]

__device__ __forceinline__ ull pack2(float v) {
    ull r;
    asm("mov.b64 %0, {%1, %1};" : "=l"(r) : "f"(v));
    return r;
}
__device__ __forceinline__ void fma2(ull& d, ull a, ull b) {
    asm("fma.rn.f32x2 %0, %1, %2, %0;" : "+l"(d) : "l"(a), "l"(b));
}
__device__ __forceinline__ float2 unpack2(ull v) {
    float2 r;
    asm("mov.b64 {%0, %1}, %2;" : "=f"(r.x), "=f"(r.y) : "l"(v));
    return r;
}

// g(d) = 2e/(1+e), e = exp(-|d|). ~2 ulp via MUFU ex2 + rcp.
__device__ __forceinline__ float gfun(float d) {
    float e = __expf(-fabsf(d));
    return __fdividef(2.0f * e, 1.0f + e);
}

__global__ void cadj_kernel(const float* __restrict__ x) {
    int idx = blockIdx.x * blockDim.x + threadIdx.x;   // 0 .. B*N-1
    int b = idx >> 12;
    int n = idx & (NN - 1);
    const float* p = x + (size_t)b * CC * NN + n;
    float s = 0.0f;
#pragma unroll
    for (int c = 0; c < CC; ++c) s += p[(size_t)c * NN];
    g_cadj[idx] = s * (1.0f / CC);
}

__global__ void __launch_bounds__(NTHREADS) gcn_kernel(
    const float* __restrict__ x, const float* __restrict__ para,
    const float* __restrict__ adj, float* __restrict__ out)
{
    __shared__ __align__(16) float w_s[JC][MTILE];   // 16 KB: A-tile [jc][m]
    __shared__ __align__(16) float fea_s[JC][36];    // fea transposed [jc][c], padded stride
    __shared__ float cm_s[MTILE];                    // cadj for this m-tile

    const int b = blockIdx.y;
    const int m_base = blockIdx.x * MTILE;
    const int tid = threadIdx.x;
    const int cg = tid >> 5;          // warp -> c-group (8 channels)
    const int lane = tid & 31;        // lane -> m-group (4 consecutive m)
    const int c0 = cg << 3;
    const int m0 = lane << 2;

    cm_s[tid] = g_cadj[b * NN + m_base + tid];   // NTHREADS == MTILE

    const float* feaB = x + (size_t)b * CC * NN;
    const float* cadjB = g_cadj + b * NN;

    ull acc[4][4];
#pragma unroll
    for (int i = 0; i < 4; ++i)
#pragma unroll
        for (int j = 0; j < 4; ++j) acc[i][j] = 0ULL;

    for (int j0 = 0; j0 < NN; j0 += JC) {
        __syncthreads();   // previous FMA phase done (and cm_s visible on iter 0)

        // ---- stage fea: transpose 32c x 32j into fea_s[jc][c] ----
#pragma unroll
        for (int it = 0; it < 2; ++it) {
            int i = tid + it * NTHREADS;          // 0..255
            int ccc = i >> 3;
            int jj = (i & 7) << 2;
            float4 f = *reinterpret_cast<const float4*>(&feaB[(size_t)ccc * NN + j0 + jj]);
            fea_s[jj + 0][ccc] = f.x;
            fea_s[jj + 1][ccc] = f.y;
            fea_s[jj + 2][ccc] = f.z;
            fea_s[jj + 3][ccc] = f.w;
        }

        // ---- stage w: w_s[jc][m] = adj[j,m] * g(cm - cj) ----
#pragma unroll
        for (int it = 0; it < 8; ++it) {
            int i = tid + it * NTHREADS;          // 0..1023
            int jc = i >> 5;
            int m4 = (i & 31) << 2;
            int jg = j0 + jc;
            float cj = __ldg(&cadjB[jg]);         // warp-broadcast
            float4 a4 = *reinterpret_cast<const float4*>(&adj[(size_t)jg * NN + m_base + m4]);
            float4 w4;
            w4.x = a4.x * gfun(cm_s[m4 + 0] - cj);
            w4.y = a4.y * gfun(cm_s[m4 + 1] - cj);
            w4.z = a4.z * gfun(cm_s[m4 + 2] - cj);
            w4.w = a4.w * gfun(cm_s[m4 + 3] - cj);
            *reinterpret_cast<float4*>(&w_s[jc][m4]) = w4;
        }
        __syncthreads();

        // ---- FMA phase: 8c x 4m register tile, packed f32x2 FMAs ----
#pragma unroll 4
        for (int jc = 0; jc < JC; ++jc) {
            ulonglong2 f1 = *reinterpret_cast<const ulonglong2*>(&fea_s[jc][c0]);      // broadcast
            ulonglong2 f2 = *reinterpret_cast<const ulonglong2*>(&fea_s[jc][c0 + 4]);  // broadcast
            float4 wv = *reinterpret_cast<const float4*>(&w_s[jc][m0]);                // conflict-free
            ull wp[4];
            wp[0] = pack2(wv.x); wp[1] = pack2(wv.y);
            wp[2] = pack2(wv.z); wp[3] = pack2(wv.w);
            ull fp[4];
            fp[0] = f1.x; fp[1] = f1.y; fp[2] = f2.x; fp[3] = f2.y;
#pragma unroll
            for (int cp = 0; cp < 4; ++cp)
#pragma unroll
                for (int mi = 0; mi < 4; ++mi)
                    fma2(acc[cp][mi], fp[cp], wp[mi]);
        }
    }

    // ---- epilogue: * para, relu, store ----
    float* outB = out + (size_t)b * CC * NN;
#pragma unroll
    for (int cp = 0; cp < 4; ++cp) {
        int ce = c0 + 2 * cp;
#pragma unroll
        for (int mi = 0; mi < 4; ++mi) {
            int m = m_base + m0 + mi;
            float2 v = unpack2(acc[cp][mi]);
            float pe = para[ce * NN + m];
            float po = para[(ce + 1) * NN + m];
            outB[(size_t)ce * NN + m]       = fmaxf(v.x * pe, 0.0f);
            outB[(size_t)(ce + 1) * NN + m] = fmaxf(v.y * po, 0.0f);
        }
    }
}

extern "C" void kernel_launch(void* const* d_in, const int* in_sizes, int n_in,
                              void* d_out, int out_size)
{
    const float* x    = (const float*)d_in[0];   // [8,32,64,64]
    const float* para = (const float*)d_in[1];   // [1,32,64,64]
    const float* adj  = (const float*)d_in[2];   // [4096,4096]
    float* out = (float*)d_out;                  // [8,32,64,64]

    cadj_kernel<<<(BB * NN) / 256, 256>>>(x);

    dim3 grid(NN / MTILE, BB);   // 32 x 8 = 256 CTAs
    gcn_kernel<<<grid, NTHREADS>>>(x, para, adj, out);
}